// round 9
// baseline (speedup 1.0000x reference)
#include <cuda_runtime.h>
#include <cuda_bf16.h>
#include <cstdint>

// Problem shapes (fixed by setup_inputs)
constexpr int T_TOK = 8192;
constexpr int H_DIM = 2048;
constexpr int I_DIM = 8192;
constexpr int N_EXP = 8;
constexpr int CAP   = 1280;

constexpr int MT_N  = CAP / 128;      // 10 m-tiles (128-row) per expert
constexpr int KI1   = H_DIM / 32;     // 64  k-iters gemm1
constexpr int KI2   = I_DIM / 32;     // 256 k-iters gemm2
constexpr int NT1   = I_DIM / 128;    // 64  128-col B tiles gemm1
constexpr int NT2   = H_DIM / 128;    // 16  128-col B tiles gemm2

// ---------------------------------------------------------------------------
// Device-global scratch (fragment-permuted tf32 operand tiles)
// tile = 4096 u32 = one 128(rows) x 32(k) A-tile or 32(k) x 128(n) B-tile
// NOTE: device-code references only (host-side use binds the host shadow).
// ---------------------------------------------------------------------------
__device__ uint32_t g_wiP[(size_t)N_EXP * NT1 * KI1 * 4096];  // 512MiB
__device__ uint32_t g_woP[(size_t)N_EXP * NT2 * KI2 * 4096];  // 512MiB
__device__ uint32_t g_aP [(size_t)N_EXP * MT_N * KI1 * 4096]; //  80MiB
__device__ uint32_t g_hP [(size_t)N_EXP * MT_N * KI2 * 4096]; // 320MiB
__device__ int   g_top1[T_TOK];
__device__ float g_wt[T_TOK];
__device__ int   g_token_of_slot[N_EXP * CAP];
__device__ float g_slot_wt[N_EXP * CAP];
__device__ int   g_counts[N_EXP];

// ---------------------------------------------------------------------------
// helpers
// ---------------------------------------------------------------------------
__device__ __forceinline__ uint32_t f2tf32(float f) {
    uint32_t u;
    asm("cvt.rna.tf32.f32 %0, %1;" : "=r"(u) : "f"(f));
    return u;
}
__device__ __forceinline__ void mma_tf32(float* c,
                                         uint32_t a0, uint32_t a1, uint32_t a2, uint32_t a3,
                                         uint32_t b0, uint32_t b1) {
    asm volatile(
        "mma.sync.aligned.m16n8k8.row.col.f32.tf32.tf32.f32 "
        "{%0,%1,%2,%3}, {%4,%5,%6,%7}, {%8,%9}, {%0,%1,%2,%3};"
        : "+f"(c[0]), "+f"(c[1]), "+f"(c[2]), "+f"(c[3])
        : "r"(a0), "r"(a1), "r"(a2), "r"(a3), "r"(b0), "r"(b1));
}
__device__ __forceinline__ uint32_t smem_u32(const void* p) {
    uint32_t a;
    asm("{ .reg .u64 t; cvta.to.shared.u64 t, %1; cvt.u32.u64 %0, t; }"
        : "=r"(a) : "l"(p));
    return a;
}
__device__ __forceinline__ void cp16(uint32_t dst, const void* src) {
    asm volatile("cp.async.cg.shared.global [%0], [%1], 16;"
                 :: "r"(dst), "l"(src) : "memory");
}
__device__ __forceinline__ void cp_commit() {
    asm volatile("cp.async.commit_group;" ::: "memory");
}
template <int N>
__device__ __forceinline__ void cp_wait() {
    asm volatile("cp.async.wait_group %0;" :: "n"(N) : "memory");
}
__device__ __forceinline__ float gelu_exact(float x) {
    return 0.5f * x * (1.f + erff(x * 0.7071067811865475f));
}

// ---------------------------------------------------------------------------
// Gating + capacity ranking (verified)
// ---------------------------------------------------------------------------
__global__ void gate_kernel(const float* __restrict__ tokens,
                            const float* __restrict__ gw) {
    int warp = threadIdx.x >> 5;
    int lane = threadIdx.x & 31;
    int t = blockIdx.x * 8 + warp;
    if (t >= T_TOK) return;
    const float* x = tokens + (size_t)t * H_DIM;
    float acc[N_EXP];
#pragma unroll
    for (int e = 0; e < N_EXP; e++) acc[e] = 0.f;
    for (int k = lane; k < H_DIM; k += 32) {
        float xv = x[k];
#pragma unroll
        for (int e = 0; e < N_EXP; e++)
            acc[e] = fmaf(xv, gw[e * H_DIM + k], acc[e]);
    }
#pragma unroll
    for (int off = 16; off; off >>= 1)
#pragma unroll
        for (int e = 0; e < N_EXP; e++)
            acc[e] += __shfl_xor_sync(0xffffffffu, acc[e], off);
    if (lane == 0) {
        int best = 0; float bv = acc[0];
#pragma unroll
        for (int e = 1; e < N_EXP; e++)
            if (acc[e] > bv) { bv = acc[e]; best = e; }
        float s = 0.f;
#pragma unroll
        for (int e = 0; e < N_EXP; e++) s += expf(acc[e] - bv);
        g_top1[t] = best;
        g_wt[t]   = 1.f / s;
    }
}

__global__ void rank_kernel() {
    __shared__ int sc[1024][N_EXP];
    int tid = threadIdx.x;
    for (int s = tid; s < N_EXP * CAP; s += 1024) g_token_of_slot[s] = -1;
    int el[8], cnt[N_EXP];
#pragma unroll
    for (int e = 0; e < N_EXP; e++) cnt[e] = 0;
#pragma unroll
    for (int i = 0; i < 8; i++) {
        int t = tid * 8 + i;
        int e = g_top1[t];
        el[i] = e; cnt[e]++;
    }
#pragma unroll
    for (int e = 0; e < N_EXP; e++) sc[tid][e] = cnt[e];
    __syncthreads();
    for (int off = 1; off < 1024; off <<= 1) {
        int v[N_EXP];
        if (tid >= off)
#pragma unroll
            for (int e = 0; e < N_EXP; e++) v[e] = sc[tid - off][e];
        __syncthreads();
        if (tid >= off)
#pragma unroll
            for (int e = 0; e < N_EXP; e++) sc[tid][e] += v[e];
        __syncthreads();
    }
    int base[N_EXP];
#pragma unroll
    for (int e = 0; e < N_EXP; e++) base[e] = sc[tid][e] - cnt[e];
#pragma unroll
    for (int i = 0; i < 8; i++) {
        int t = tid * 8 + i;
        int e = el[i];
        int r = base[e]++;
        if (r < CAP) {
            g_token_of_slot[e * CAP + r] = t;
            g_slot_wt[e * CAP + r]       = g_wt[t];
        }
    }
    if (tid == 1023)
#pragma unroll
        for (int e = 0; e < N_EXP; e++) g_counts[e] = min(sc[1023][e], CAP);
}

// ---------------------------------------------------------------------------
// prep_w: [E][K][N] fp32 -> fragment-permuted tf32 B-tiles (verified)
// ---------------------------------------------------------------------------
__global__ __launch_bounds__(256)
void prep_w(const float* __restrict__ src, int which, int K, int N) {
    __shared__ float ts[32][136];
    uint32_t* __restrict__ dstBase = which ? g_woP : g_wiP;  // device-side bind
    int e = blockIdx.z;
    int n0 = blockIdx.x * 128, k0 = blockIdx.y * 32;
    const float* s = src + ((size_t)e * K + k0) * N + n0;
    int t = threadIdx.x;
#pragma unroll
    for (int i = 0; i < 16; i++) {
        int f = t + 256 * i;
        int r = f >> 7, c = f & 127;
        ts[r][c] = s[(size_t)r * N + c];
    }
    __syncthreads();
    size_t base = (((size_t)e * gridDim.x + blockIdx.x) * gridDim.y
                   + blockIdx.y) * 4096;
    uint32_t* d = dstBase + base;
#pragma unroll
    for (int j = 0; j < 8; j++) {
        int q  = t + 256 * j;
        int ln = q & 31;
        int g  = q >> 5;
        int nt = g & 15, kk = g >> 4;
        int n  = nt * 8 + (ln >> 2);
        int k  = kk * 8 + (ln & 3);
        uint2 v;
        v.x = f2tf32(ts[k][n]);
        v.y = f2tf32(ts[k + 4][n]);
        *(uint2*)(d + (size_t)q * 2) = v;
    }
}

// ---------------------------------------------------------------------------
// dispatch_aP: gather token rows -> fragment-permuted tf32 A-tiles (verified)
// ---------------------------------------------------------------------------
__global__ __launch_bounds__(256)
void dispatch_aP(const float* __restrict__ tokens) {
    __shared__ float ts[128][36];
    int e = blockIdx.z, mT = blockIdx.y, kI = blockIdx.x;
    int k0 = kI * 32;
    int t = threadIdx.x;
#pragma unroll
    for (int i = 0; i < 4; i++) {
        int f = t + 256 * i;
        int row = f >> 3, c4 = (f & 7) * 4;
        int tok = g_token_of_slot[e * CAP + mT * 128 + row];
        float4 v = (tok >= 0)
                 ? *(const float4*)(tokens + (size_t)tok * H_DIM + k0 + c4)
                 : make_float4(0.f, 0.f, 0.f, 0.f);
        *(float4*)&ts[row][c4] = v;
    }
    __syncthreads();
    uint32_t* d = g_aP + (((size_t)e * MT_N + mT) * KI1 + kI) * 4096;
    int ln = t & 31, mt = t >> 5;
    int r = ln >> 2, b = ln & 3;
#pragma unroll
    for (int j = 0; j < 4; j++) {
        int row = mt * 16 + r;
        int k = j * 8 + b;
        uint4 v;
        v.x = f2tf32(ts[row][k]);
        v.y = f2tf32(ts[row + 8][k]);
        v.z = f2tf32(ts[row][k + 4]);
        v.w = f2tf32(ts[row + 8][k + 4]);
        *(uint4*)(d + (size_t)(t + 256 * j) * 4) = v;
    }
}

// ---------------------------------------------------------------------------
// GEMM core: fat CTA tiles (gemm1 128x256, gemm2 256x128), 64x64 warp tiles,
// 2-stage cp.async pipeline (48KB/stage -> 96KB -> 2 CTA/SM).
// ---------------------------------------------------------------------------
#define TILE_B 16384
#define STG_B  49152

// copy one 16KB permuted tile (256 thr x 64B)
__device__ __forceinline__ void copy_tile(uint32_t dstBase, int t,
                                          const uint32_t* src) {
    uint32_t d = dstBase + t * 64;
    const uint32_t* s = src + t * 16;
#pragma unroll
    for (int j = 0; j < 4; j++) cp16(d + j * 16, s + j * 4);
}

// consume one stage with a 64x64 warp tile
__device__ __forceinline__ void consume64(uint32_t stage, int lane,
                                          uint32_t aOff, int mloc,
                                          uint32_t bOff, int nloc,
                                          float acc[4][8][4]) {
#pragma unroll
    for (int kk = 0; kk < 4; kk++) {
        uint4 af[4];
        uint2 bf[8];
#pragma unroll
        for (int mt = 0; mt < 4; mt++) {
            uint32_t addr = stage + aOff
                          + (((kk * 8 + mloc + mt) * 32 + lane) << 4);
            asm volatile("ld.shared.v4.b32 {%0,%1,%2,%3}, [%4];"
                         : "=r"(af[mt].x), "=r"(af[mt].y),
                           "=r"(af[mt].z), "=r"(af[mt].w) : "r"(addr));
        }
#pragma unroll
        for (int nt = 0; nt < 8; nt++) {
            uint32_t addr = stage + bOff
                          + (((kk * 16 + nloc + nt) * 32 + lane) << 3);
            asm volatile("ld.shared.v2.b32 {%0,%1}, [%2];"
                         : "=r"(bf[nt].x), "=r"(bf[nt].y) : "r"(addr));
        }
#pragma unroll
        for (int mt = 0; mt < 4; mt++)
#pragma unroll
            for (int nt = 0; nt < 8; nt++)
                mma_tf32(acc[mt][nt], af[mt].x, af[mt].y, af[mt].z, af[mt].w,
                         bf[nt].x, bf[nt].y);
    }
}

// GEMM1: A(128 x H) @ Wi(H x 256-col slab) -> gelu -> g_hP (frag-permuted)
// grid (MT_N, I_DIM/256, E): mT fastest
__global__ __launch_bounds__(256, 2)
void gemm1_tc(float* dummy) {
    extern __shared__ char smem[];
    uint32_t sbase = smem_u32(smem);

    int e = blockIdx.z;
    int cnt = g_counts[e];
    int mT = blockIdx.x;                 // 128-row tile
    if (mT * 128 >= cnt) return;
    int nT = blockIdx.y;                 // 256-col slab

    int t = threadIdx.x;
    int lane = t & 31, w = t >> 5;
    int wm = w >> 2, wn = w & 3;         // 2 x 4 warp grid

    const uint32_t* aSrc  = g_aP  + (((size_t)e * MT_N + mT) * KI1) * 4096;
    const uint32_t* bSrc0 = g_wiP + (((size_t)e * NT1 + nT * 2) * KI1) * 4096;
    const uint32_t* bSrc1 = bSrc0 + (size_t)KI1 * 4096;

    float acc[4][8][4];
#pragma unroll
    for (int a = 0; a < 4; a++)
#pragma unroll
        for (int b = 0; b < 8; b++)
#pragma unroll
            for (int c = 0; c < 4; c++) acc[a][b][c] = 0.f;

#pragma unroll
    for (int p = 0; p < 2; p++) {
        uint32_t st = sbase + p * STG_B;
        copy_tile(st,              t, aSrc  + (size_t)p * 4096);
        copy_tile(st + TILE_B,     t, bSrc0 + (size_t)p * 4096);
        copy_tile(st + 2 * TILE_B, t, bSrc1 + (size_t)p * 4096);
        cp_commit();
    }
    uint32_t aOff = 0;
    uint32_t bOff = TILE_B + ((uint32_t)(wn >> 1)) * TILE_B;
    int mloc = wm * 4;
    int nloc = (wn & 1) * 8;
    for (int it = 0; it < KI1; ++it) {
        int s = it & 1;
        uint32_t st = sbase + s * STG_B;
        cp_wait<1>();
        __syncthreads();
        consume64(st, lane, aOff, mloc, bOff, nloc, acc);
        __syncthreads();
        if (it + 2 < KI1) {
            copy_tile(st,              t, aSrc  + (size_t)(it + 2) * 4096);
            copy_tile(st + TILE_B,     t, bSrc0 + (size_t)(it + 2) * 4096);
            copy_tile(st + 2 * TILE_B, t, bSrc1 + (size_t)(it + 2) * 4096);
        }
        cp_commit();
    }
    cp_wait<0>();
    __syncthreads();

    // epilogue: gelu -> fragment-permuted g_hP, two 128-col bounce phases
    float* eb = (float*)smem;            // [128][132]
    int rr = lane >> 2, bb = lane & 3;
#pragma unroll
    for (int p = 0; p < 2; p++) {
        if ((wn >> 1) == p) {
            int colbase = (wn & 1) * 64;
#pragma unroll
            for (int mt = 0; mt < 4; mt++) {
                int row = wm * 64 + mt * 16 + rr;
#pragma unroll
                for (int nt = 0; nt < 8; nt++) {
                    int col = colbase + nt * 8 + 2 * bb;
                    float2 v0, v1;
                    v0.x = gelu_exact(acc[mt][nt][0]);
                    v0.y = gelu_exact(acc[mt][nt][1]);
                    v1.x = gelu_exact(acc[mt][nt][2]);
                    v1.y = gelu_exact(acc[mt][nt][3]);
                    *(float2*)&eb[row * 132 + col]       = v0;
                    *(float2*)&eb[(row + 8) * 132 + col] = v1;
                }
            }
        }
        __syncthreads();
        int mt8 = t >> 5;
#pragma unroll
        for (int kl = 0; kl < 4; kl++) {
            int kI = nT * 8 + p * 4 + kl;
            uint32_t* d = g_hP + (((size_t)e * MT_N + mT) * KI2 + kI) * 4096;
#pragma unroll
            for (int j = 0; j < 4; j++) {   // j = kk
                int row = mt8 * 16 + rr;
                int c = kl * 32 + j * 8 + bb;
                uint4 v;
                v.x = f2tf32(eb[row * 132 + c]);
                v.y = f2tf32(eb[(row + 8) * 132 + c]);
                v.z = f2tf32(eb[row * 132 + c + 4]);
                v.w = f2tf32(eb[(row + 8) * 132 + c + 4]);
                *(uint4*)(d + (size_t)(t + 256 * j) * 4) = v;
            }
        }
        __syncthreads();
    }
}

// GEMM2: g_hP(256 rows) @ Wo(I x 128-col) -> weight-scaled scatter to out
// grid (MT_N/2, NT2, E): mT fastest
__global__ __launch_bounds__(256, 2)
void gemm2_tc(float* __restrict__ outp) {
    extern __shared__ char smem[];
    uint32_t sbase = smem_u32(smem);

    int e = blockIdx.z;
    int cnt = g_counts[e];
    int mT = blockIdx.x;                 // 256-row slab
    if (mT * 256 >= cnt) return;
    int nT = blockIdx.y;
    int n0 = nT * 128;

    int t = threadIdx.x;
    int lane = t & 31, w = t >> 5;
    int wm = w >> 1, wn = w & 1;         // 4 x 2 warp grid

    const uint32_t* aSrc0 = g_hP + (((size_t)e * MT_N + mT * 2) * KI2) * 4096;
    const uint32_t* aSrc1 = aSrc0 + (size_t)KI2 * 4096;
    const uint32_t* bSrc  = g_woP + (((size_t)e * NT2 + nT) * KI2) * 4096;

    float acc[4][8][4];
#pragma unroll
    for (int a = 0; a < 4; a++)
#pragma unroll
        for (int b = 0; b < 8; b++)
#pragma unroll
            for (int c = 0; c < 4; c++) acc[a][b][c] = 0.f;

#pragma unroll
    for (int p = 0; p < 2; p++) {
        uint32_t st = sbase + p * STG_B;
        copy_tile(st,              t, aSrc0 + (size_t)p * 4096);
        copy_tile(st + TILE_B,     t, aSrc1 + (size_t)p * 4096);
        copy_tile(st + 2 * TILE_B, t, bSrc  + (size_t)p * 4096);
        cp_commit();
    }
    uint32_t aOff = ((uint32_t)(wm >> 1)) * TILE_B;
    uint32_t bOff = 2 * TILE_B;
    int mloc = (wm & 1) * 4;
    int nloc = wn * 8;
    for (int it = 0; it < KI2; ++it) {
        int s = it & 1;
        uint32_t st = sbase + s * STG_B;
        cp_wait<1>();
        __syncthreads();
        consume64(st, lane, aOff, mloc, bOff, nloc, acc);
        __syncthreads();
        if (it + 2 < KI2) {
            copy_tile(st,              t, aSrc0 + (size_t)(it + 2) * 4096);
            copy_tile(st + TILE_B,     t, aSrc1 + (size_t)(it + 2) * 4096);
            copy_tile(st + 2 * TILE_B, t, bSrc  + (size_t)(it + 2) * 4096);
        }
        cp_commit();
    }
    cp_wait<0>();

    // epilogue: weight * acc scattered to out rows (256 rows per CTA)
    int rr = lane >> 2, bb = lane & 3;
    int m0 = mT * 256;
#pragma unroll
    for (int mt = 0; mt < 4; mt++) {
#pragma unroll
        for (int h = 0; h < 2; h++) {
            int m = m0 + wm * 64 + mt * 16 + rr + 8 * h;
            int tok = g_token_of_slot[e * CAP + m];
            if (tok < 0) continue;
            float wgt = g_slot_wt[e * CAP + m];
            float* orow = outp + (size_t)tok * H_DIM + n0 + wn * 64;
#pragma unroll
            for (int nt = 0; nt < 8; nt++) {
                float2 v;
                v.x = wgt * acc[mt][nt][2 * h];
                v.y = wgt * acc[mt][nt][2 * h + 1];
                *(float2*)&orow[nt * 8 + 2 * bb] = v;
            }
        }
    }
}

__global__ void zero_kernel(float* __restrict__ p, size_t n) {
    size_t i = (size_t)blockIdx.x * blockDim.x + threadIdx.x;
    size_t stride = (size_t)gridDim.x * blockDim.x;
    for (; i < n; i += stride) p[i] = 0.f;
}

extern "C" void kernel_launch(void* const* d_in, const int* in_sizes, int n_in,
                              void* d_out, int out_size) {
    const float* tokens = (const float*)d_in[0];
    const float* gw     = (const float*)d_in[1];
    const float* wi     = (const float*)d_in[2];
    const float* wo     = (const float*)d_in[3];
    float* outp = (float*)d_out;

    const int SMEM = 2 * STG_B;   // 98304 -> 2 CTA/SM
    cudaFuncSetAttribute(gemm1_tc, cudaFuncAttributeMaxDynamicSharedMemorySize, SMEM);
    cudaFuncSetAttribute(gemm2_tc, cudaFuncAttributeMaxDynamicSharedMemorySize, SMEM);

    gate_kernel<<<T_TOK / 8, 256>>>(tokens, gw);
    rank_kernel<<<1, 1024>>>();
    prep_w<<<dim3(NT1, KI1, N_EXP), 256>>>(wi, /*which=*/0, H_DIM, I_DIM);
    prep_w<<<dim3(NT2, KI2, N_EXP), 256>>>(wo, /*which=*/1, I_DIM, H_DIM);
    dispatch_aP<<<dim3(KI1, MT_N, N_EXP), 256>>>(tokens);
    gemm1_tc<<<dim3(MT_N, I_DIM / 256, N_EXP), 256, SMEM>>>(nullptr);
    zero_kernel<<<1024, 256>>>(outp, (size_t)T_TOK * H_DIM);
    gemm2_tc<<<dim3(MT_N / 2, NT2, N_EXP), 256, SMEM>>>(outp);
}

// round 10
// speedup vs baseline: 3.2777x; 3.2777x over previous
#include <cuda_runtime.h>
#include <cuda_bf16.h>
#include <cstdint>

// Problem shapes (fixed by setup_inputs)
constexpr int T_TOK = 8192;
constexpr int H_DIM = 2048;
constexpr int I_DIM = 8192;
constexpr int N_EXP = 8;
constexpr int CAP   = 1280;

constexpr int MT_N  = CAP / 128;      // 10 m-tiles per expert
constexpr int KI1   = H_DIM / 32;     // 64  k-iters gemm1
constexpr int KI2   = I_DIM / 32;     // 256 k-iters gemm2
constexpr int NT1   = I_DIM / 128;    // 64  n-tiles gemm1
constexpr int NT2   = H_DIM / 128;    // 16  n-tiles gemm2

// ---------------------------------------------------------------------------
// Device-global scratch (fragment-permuted tf32 operand tiles)
// tile = 4096 u32 = one 128(rows) x 32(k) A-tile or 32(k) x 128(n) B-tile
// NOTE: device-code references only (host-side use binds the host shadow).
// ---------------------------------------------------------------------------
__device__ uint32_t g_wiP[(size_t)N_EXP * NT1 * KI1 * 4096];  // 512MiB
__device__ uint32_t g_woP[(size_t)N_EXP * NT2 * KI2 * 4096];  // 512MiB
__device__ uint32_t g_aP [(size_t)N_EXP * MT_N * KI1 * 4096]; //  80MiB
__device__ uint32_t g_hP [(size_t)N_EXP * MT_N * KI2 * 4096]; // 320MiB
__device__ int   g_top1[T_TOK];
__device__ float g_wt[T_TOK];
__device__ int   g_token_of_slot[N_EXP * CAP];
__device__ float g_slot_wt[N_EXP * CAP];
__device__ int   g_counts[N_EXP];

// ---------------------------------------------------------------------------
// helpers
// ---------------------------------------------------------------------------
__device__ __forceinline__ uint32_t f2tf32(float f) {
    uint32_t u;
    asm("cvt.rna.tf32.f32 %0, %1;" : "=r"(u) : "f"(f));
    return u;
}
__device__ __forceinline__ void mma_tf32(float* c,
                                         uint32_t a0, uint32_t a1, uint32_t a2, uint32_t a3,
                                         uint32_t b0, uint32_t b1) {
    asm volatile(
        "mma.sync.aligned.m16n8k8.row.col.f32.tf32.tf32.f32 "
        "{%0,%1,%2,%3}, {%4,%5,%6,%7}, {%8,%9}, {%0,%1,%2,%3};"
        : "+f"(c[0]), "+f"(c[1]), "+f"(c[2]), "+f"(c[3])
        : "r"(a0), "r"(a1), "r"(a2), "r"(a3), "r"(b0), "r"(b1));
}
__device__ __forceinline__ uint32_t smem_u32(const void* p) {
    uint32_t a;
    asm("{ .reg .u64 t; cvta.to.shared.u64 t, %1; cvt.u32.u64 %0, t; }"
        : "=r"(a) : "l"(p));
    return a;
}
__device__ __forceinline__ void mbar_init(uint32_t a, uint32_t cnt) {
    asm volatile("mbarrier.init.shared.b64 [%0], %1;" :: "r"(a), "r"(cnt) : "memory");
}
__device__ __forceinline__ void mbar_expect(uint32_t a, uint32_t tx) {
    asm volatile("mbarrier.arrive.expect_tx.shared.b64 _, [%0], %1;"
                 :: "r"(a), "r"(tx) : "memory");
}
__device__ __forceinline__ void bulk_g2s(uint32_t dst, const void* src,
                                         uint32_t bytes, uint32_t mbar) {
    asm volatile(
        "cp.async.bulk.shared::cta.global.mbarrier::complete_tx::bytes "
        "[%0], [%1], %2, [%3];"
        :: "r"(dst), "l"(src), "r"(bytes), "r"(mbar) : "memory");
}
__device__ __forceinline__ void mbar_wait(uint32_t a, uint32_t ph) {
    asm volatile(
        "{\n\t.reg .pred P;\n\t"
        "W%=:\n\t"
        "mbarrier.try_wait.parity.shared.b64 P, [%0], %1;\n\t"
        "@!P bra W%=;\n\t}"
        :: "r"(a), "r"(ph) : "memory");
}
__device__ __forceinline__ float gelu_exact(float x) {
    return 0.5f * x * (1.f + erff(x * 0.7071067811865475f));
}

// ---------------------------------------------------------------------------
// Fused prep_wi + gating kernel (grid-partitioned) so gemm1 is our 4th launch
// blocks [0, 32768): permute wi;  blocks [32768, 33792): gating (8 tok/block)
// ---------------------------------------------------------------------------
__global__ __launch_bounds__(256)
void prep_wi_gate(const float* __restrict__ tokens,
                  const float* __restrict__ gw,
                  const float* __restrict__ wi) {
    __shared__ float ts[32][136];
    int bid = blockIdx.x;
    int t = threadIdx.x;
    if (bid < 32768) {
        int e = bid >> 12;
        int rem = bid & 4095;
        int bx = rem >> 6;          // n-tile 0..63
        int by = rem & 63;          // k-tile 0..63
        int n0 = bx * 128, k0 = by * 32;
        const float* s = wi + ((size_t)e * H_DIM + k0) * I_DIM + n0;
#pragma unroll
        for (int i = 0; i < 16; i++) {
            int f = t + 256 * i;
            int r = f >> 7, c = f & 127;
            ts[r][c] = s[(size_t)r * I_DIM + c];
        }
        __syncthreads();
        size_t base = (((size_t)e * 64 + bx) * 64 + by) * 4096;
        uint32_t* d = g_wiP + base;
#pragma unroll
        for (int j = 0; j < 8; j++) {
            int q  = t + 256 * j;
            int ln = q & 31;
            int g  = q >> 5;
            int nt = g & 15, kk = g >> 4;
            int n  = nt * 8 + (ln >> 2);
            int k  = kk * 8 + (ln & 3);
            uint2 v;
            v.x = f2tf32(ts[k][n]);
            v.y = f2tf32(ts[k + 4][n]);
            *(uint2*)(d + (size_t)q * 2) = v;
        }
    } else {
        int warp = t >> 5;
        int lane = t & 31;
        int tok = (bid - 32768) * 8 + warp;
        if (tok >= T_TOK) return;
        const float* x = tokens + (size_t)tok * H_DIM;
        float acc[N_EXP];
#pragma unroll
        for (int e = 0; e < N_EXP; e++) acc[e] = 0.f;
        for (int k = lane; k < H_DIM; k += 32) {
            float xv = x[k];
#pragma unroll
            for (int e = 0; e < N_EXP; e++)
                acc[e] = fmaf(xv, gw[e * H_DIM + k], acc[e]);
        }
#pragma unroll
        for (int off = 16; off; off >>= 1)
#pragma unroll
            for (int e = 0; e < N_EXP; e++)
                acc[e] += __shfl_xor_sync(0xffffffffu, acc[e], off);
        if (lane == 0) {
            int best = 0; float bv = acc[0];
#pragma unroll
            for (int e = 1; e < N_EXP; e++)
                if (acc[e] > bv) { bv = acc[e]; best = e; }
            float s = 0.f;
#pragma unroll
            for (int e = 0; e < N_EXP; e++) s += expf(acc[e] - bv);
            g_top1[tok] = best;
            g_wt[tok]   = 1.f / s;
        }
    }
}

// ---------------------------------------------------------------------------
// rank_kernel (verified)
// ---------------------------------------------------------------------------
__global__ void rank_kernel() {
    __shared__ int sc[1024][N_EXP];
    int tid = threadIdx.x;
    for (int s = tid; s < N_EXP * CAP; s += 1024) g_token_of_slot[s] = -1;
    int el[8], cnt[N_EXP];
#pragma unroll
    for (int e = 0; e < N_EXP; e++) cnt[e] = 0;
#pragma unroll
    for (int i = 0; i < 8; i++) {
        int t = tid * 8 + i;
        int e = g_top1[t];
        el[i] = e; cnt[e]++;
    }
#pragma unroll
    for (int e = 0; e < N_EXP; e++) sc[tid][e] = cnt[e];
    __syncthreads();
    for (int off = 1; off < 1024; off <<= 1) {
        int v[N_EXP];
        if (tid >= off)
#pragma unroll
            for (int e = 0; e < N_EXP; e++) v[e] = sc[tid - off][e];
        __syncthreads();
        if (tid >= off)
#pragma unroll
            for (int e = 0; e < N_EXP; e++) sc[tid][e] += v[e];
        __syncthreads();
    }
    int base[N_EXP];
#pragma unroll
    for (int e = 0; e < N_EXP; e++) base[e] = sc[tid][e] - cnt[e];
#pragma unroll
    for (int i = 0; i < 8; i++) {
        int t = tid * 8 + i;
        int e = el[i];
        int r = base[e]++;
        if (r < CAP) {
            g_token_of_slot[e * CAP + r] = t;
            g_slot_wt[e * CAP + r]       = g_wt[t];
        }
    }
    if (tid == 1023)
#pragma unroll
        for (int e = 0; e < N_EXP; e++) g_counts[e] = min(sc[1023][e], CAP);
}

// ---------------------------------------------------------------------------
// prep_w (wo only now): [E][K][N] fp32 -> fragment-permuted tf32 B-tiles
// ---------------------------------------------------------------------------
__global__ __launch_bounds__(256)
void prep_w(const float* __restrict__ src, int which, int K, int N) {
    __shared__ float ts[32][136];
    uint32_t* __restrict__ dstBase = which ? g_woP : g_wiP;
    int e = blockIdx.z;
    int n0 = blockIdx.x * 128, k0 = blockIdx.y * 32;
    const float* s = src + ((size_t)e * K + k0) * N + n0;
    int t = threadIdx.x;
#pragma unroll
    for (int i = 0; i < 16; i++) {
        int f = t + 256 * i;
        int r = f >> 7, c = f & 127;
        ts[r][c] = s[(size_t)r * N + c];
    }
    __syncthreads();
    size_t base = (((size_t)e * gridDim.x + blockIdx.x) * gridDim.y
                   + blockIdx.y) * 4096;
    uint32_t* d = dstBase + base;
#pragma unroll
    for (int j = 0; j < 8; j++) {
        int q  = t + 256 * j;
        int ln = q & 31;
        int g  = q >> 5;
        int nt = g & 15, kk = g >> 4;
        int n  = nt * 8 + (ln >> 2);
        int k  = kk * 8 + (ln & 3);
        uint2 v;
        v.x = f2tf32(ts[k][n]);
        v.y = f2tf32(ts[k + 4][n]);
        *(uint2*)(d + (size_t)q * 2) = v;
    }
}

// ---------------------------------------------------------------------------
// dispatch_aP (verified)
// ---------------------------------------------------------------------------
__global__ __launch_bounds__(256)
void dispatch_aP(const float* __restrict__ tokens) {
    __shared__ float ts[128][36];
    int e = blockIdx.z, mT = blockIdx.y, kI = blockIdx.x;
    int k0 = kI * 32;
    int t = threadIdx.x;
#pragma unroll
    for (int i = 0; i < 4; i++) {
        int f = t + 256 * i;
        int row = f >> 3, c4 = (f & 7) * 4;
        int tok = g_token_of_slot[e * CAP + mT * 128 + row];
        float4 v = (tok >= 0)
                 ? *(const float4*)(tokens + (size_t)tok * H_DIM + k0 + c4)
                 : make_float4(0.f, 0.f, 0.f, 0.f);
        *(float4*)&ts[row][c4] = v;
    }
    __syncthreads();
    uint32_t* d = g_aP + (((size_t)e * MT_N + mT) * KI1 + kI) * 4096;
    int ln = t & 31, mt = t >> 5;
    int r = ln >> 2, b = ln & 3;
#pragma unroll
    for (int j = 0; j < 4; j++) {
        int row = mt * 16 + r;
        int k = j * 8 + b;
        uint4 v;
        v.x = f2tf32(ts[row][k]);
        v.y = f2tf32(ts[row + 8][k]);
        v.z = f2tf32(ts[row][k + 4]);
        v.w = f2tf32(ts[row + 8][k + 4]);
        *(uint4*)(d + (size_t)(t + 256 * j) * 4) = v;
    }
}

// ---------------------------------------------------------------------------
// GEMM core: 128x128x32 tiles, 3-stage pipeline, TMA bulk producers
// (2 cp.async.bulk per stage, mbarrier completion), single barrier per k-iter.
// stage = 32KB: [A 16KB][B 16KB], 3 stages = 96KB -> 2 CTA/SM.
// ---------------------------------------------------------------------------
#define STG_B 32768

struct MmaCtx {
    uint32_t sbase;
    int lane, wm, wn;
};

__device__ __forceinline__ void consume_stage(const MmaCtx& cx, int s,
                                              float acc[4][4][4]) {
    uint32_t aB = cx.sbase + s * STG_B;
    uint32_t bB = aB + 16384;
#pragma unroll
    for (int kk = 0; kk < 4; kk++) {
        uint4 af[4];
        uint2 bf[4];
#pragma unroll
        for (int mt = 0; mt < 4; mt++) {
            uint32_t addr = aB + (((kk * 8 + cx.wm * 4 + mt) * 32 + cx.lane) << 4);
            asm volatile("ld.shared.v4.b32 {%0,%1,%2,%3}, [%4];"
                         : "=r"(af[mt].x), "=r"(af[mt].y),
                           "=r"(af[mt].z), "=r"(af[mt].w) : "r"(addr));
        }
#pragma unroll
        for (int nt = 0; nt < 4; nt++) {
            uint32_t addr = bB + (((kk * 16 + cx.wn * 4 + nt) * 32 + cx.lane) << 3);
            asm volatile("ld.shared.v2.b32 {%0,%1}, [%2];"
                         : "=r"(bf[nt].x), "=r"(bf[nt].y) : "r"(addr));
        }
#pragma unroll
        for (int mt = 0; mt < 4; mt++)
#pragma unroll
            for (int nt = 0; nt < 4; nt++)
                mma_tf32(acc[mt][nt], af[mt].x, af[mt].y, af[mt].z, af[mt].w,
                         bf[nt].x, bf[nt].y);
    }
}

// thread0 fills stage s with k-iter `it` tiles via 2 bulk copies
__device__ __forceinline__ void fill_stage(uint32_t sbase, uint32_t mbar_base,
                                           int s, const uint32_t* aSrc,
                                           const uint32_t* bSrc, int it) {
    uint32_t mb = mbar_base + s * 8;
    uint32_t st = sbase + s * STG_B;
    mbar_expect(mb, 32768);
    bulk_g2s(st,         aSrc + (size_t)it * 4096, 16384, mb);
    bulk_g2s(st + 16384, bSrc + (size_t)it * 4096, 16384, mb);
}

// GEMM1: g_aP @ g_wiP -> gelu -> g_hP (fragment-permuted). mT fastest.
__global__ __launch_bounds__(256, 2)
void gemm1_tc(float* dummy) {
    extern __shared__ char smem[];
    __shared__ __align__(8) uint64_t mbs[3];
    uint32_t sbase = smem_u32(smem);
    uint32_t mbb   = smem_u32(mbs);

    int e = blockIdx.z;
    int cnt = g_counts[e];
    int mT = blockIdx.x;
    if (mT * 128 >= cnt) return;
    int nT = blockIdx.y;

    int t = threadIdx.x;
    MmaCtx cx;
    cx.sbase = sbase;
    cx.lane = t & 31;
    int w = t >> 5;
    cx.wm = w >> 2; cx.wn = w & 3;

    const uint32_t* aSrc = g_aP  + (((size_t)e * MT_N + mT) * KI1) * 4096;
    const uint32_t* bSrc = g_wiP + (((size_t)e * NT1 + nT) * KI1) * 4096;

    if (t == 0) {
#pragma unroll
        for (int s = 0; s < 3; s++) mbar_init(mbb + s * 8, 1);
    }
    __syncthreads();
    if (t == 0) {
#pragma unroll
        for (int p = 0; p < 3; p++) fill_stage(sbase, mbb, p, aSrc, bSrc, p);
    }

    float acc[4][4][4];
#pragma unroll
    for (int a = 0; a < 4; a++)
#pragma unroll
        for (int b = 0; b < 4; b++)
#pragma unroll
            for (int c = 0; c < 4; c++) acc[a][b][c] = 0.f;

    for (int it = 0; it < KI1; ++it) {
        int s = it % 3;
        uint32_t ph = (uint32_t)((it / 3) & 1);
        mbar_wait(mbb + s * 8, ph);
        consume_stage(cx, s, acc);
        __syncthreads();
        if (it + 3 < KI1 && t == 0)
            fill_stage(sbase, mbb, s, aSrc, bSrc, it + 3);
    }
    __syncthreads();

    // epilogue: gelu -> fragment-permuted g_hP via smem bounce (128x68 f32)
    float* eb = (float*)smem;
    int ln = cx.lane;
    int rr = ln >> 2, bb = ln & 3;
#pragma unroll
    for (int half = 0; half < 2; half++) {
        if ((cx.wn >> 1) == half) {
            int colbase = (cx.wn & 1) * 32;
#pragma unroll
            for (int mt = 0; mt < 4; mt++) {
                int row = cx.wm * 64 + mt * 16 + rr;
#pragma unroll
                for (int nt = 0; nt < 4; nt++) {
                    int col = colbase + nt * 8 + 2 * bb;
                    float2 v0, v1;
                    v0.x = gelu_exact(acc[mt][nt][0]);
                    v0.y = gelu_exact(acc[mt][nt][1]);
                    v1.x = gelu_exact(acc[mt][nt][2]);
                    v1.y = gelu_exact(acc[mt][nt][3]);
                    *(float2*)&eb[row * 68 + col]       = v0;
                    *(float2*)&eb[(row + 8) * 68 + col] = v1;
                }
            }
        }
        __syncthreads();
        int mt8 = t >> 5;
#pragma unroll
        for (int kl = 0; kl < 2; kl++) {
            int kI = nT * 4 + half * 2 + kl;
            uint32_t* d = g_hP + (((size_t)e * MT_N + mT) * KI2 + kI) * 4096;
#pragma unroll
            for (int j = 0; j < 4; j++) {   // j = kk
                int row = mt8 * 16 + rr;
                int c = kl * 32 + j * 8 + bb;
                uint4 v;
                v.x = f2tf32(eb[row * 68 + c]);
                v.y = f2tf32(eb[(row + 8) * 68 + c]);
                v.z = f2tf32(eb[row * 68 + c + 4]);
                v.w = f2tf32(eb[(row + 8) * 68 + c + 4]);
                *(uint4*)(d + (size_t)(t + 256 * j) * 4) = v;
            }
        }
        __syncthreads();
    }
}

// GEMM2: g_hP @ g_woP -> weight-scaled scatter to out. mT fastest.
__global__ __launch_bounds__(256, 2)
void gemm2_tc(float* __restrict__ outp) {
    extern __shared__ char smem[];
    __shared__ __align__(8) uint64_t mbs[3];
    uint32_t sbase = smem_u32(smem);
    uint32_t mbb   = smem_u32(mbs);

    int e = blockIdx.z;
    int cnt = g_counts[e];
    int mT = blockIdx.x;
    if (mT * 128 >= cnt) return;
    int nT = blockIdx.y;
    int n0 = nT * 128;

    int t = threadIdx.x;
    MmaCtx cx;
    cx.sbase = sbase;
    cx.lane = t & 31;
    int w = t >> 5;
    cx.wm = w >> 2; cx.wn = w & 3;

    const uint32_t* aSrc = g_hP  + (((size_t)e * MT_N + mT) * KI2) * 4096;
    const uint32_t* bSrc = g_woP + (((size_t)e * NT2 + nT) * KI2) * 4096;

    if (t == 0) {
#pragma unroll
        for (int s = 0; s < 3; s++) mbar_init(mbb + s * 8, 1);
    }
    __syncthreads();
    if (t == 0) {
#pragma unroll
        for (int p = 0; p < 3; p++) fill_stage(sbase, mbb, p, aSrc, bSrc, p);
    }

    float acc[4][4][4];
#pragma unroll
    for (int a = 0; a < 4; a++)
#pragma unroll
        for (int b = 0; b < 4; b++)
#pragma unroll
            for (int c = 0; c < 4; c++) acc[a][b][c] = 0.f;

    for (int it = 0; it < KI2; ++it) {
        int s = it % 3;
        uint32_t ph = (uint32_t)((it / 3) & 1);
        mbar_wait(mbb + s * 8, ph);
        consume_stage(cx, s, acc);
        __syncthreads();
        if (it + 3 < KI2 && t == 0)
            fill_stage(sbase, mbb, s, aSrc, bSrc, it + 3);
    }

    // epilogue: weight * acc scattered to out rows
    int ln = cx.lane;
    int rr = ln >> 2, bb = ln & 3;
    int m0 = mT * 128;
#pragma unroll
    for (int mt = 0; mt < 4; mt++) {
#pragma unroll
        for (int h = 0; h < 2; h++) {
            int m = m0 + cx.wm * 64 + mt * 16 + rr + 8 * h;
            int tok = g_token_of_slot[e * CAP + m];
            if (tok < 0) continue;
            float wgt = g_slot_wt[e * CAP + m];
            float* orow = outp + (size_t)tok * H_DIM + n0 + cx.wn * 32;
#pragma unroll
            for (int nt = 0; nt < 4; nt++) {
                float2 v;
                v.x = wgt * acc[mt][nt][2 * h];
                v.y = wgt * acc[mt][nt][2 * h + 1];
                *(float2*)&orow[nt * 8 + 2 * bb] = v;
            }
        }
    }
}

__global__ void zero_kernel(float* __restrict__ p, size_t n) {
    size_t i = (size_t)blockIdx.x * blockDim.x + threadIdx.x;
    size_t stride = (size_t)gridDim.x * blockDim.x;
    for (; i < n; i += stride) p[i] = 0.f;
}

extern "C" void kernel_launch(void* const* d_in, const int* in_sizes, int n_in,
                              void* d_out, int out_size) {
    const float* tokens = (const float*)d_in[0];
    const float* gw     = (const float*)d_in[1];
    const float* wi     = (const float*)d_in[2];
    const float* wo     = (const float*)d_in[3];
    float* outp = (float*)d_out;

    const int SMEM = 3 * STG_B;   // 98304 -> 2 CTA/SM
    cudaFuncSetAttribute(gemm1_tc, cudaFuncAttributeMaxDynamicSharedMemorySize, SMEM);
    cudaFuncSetAttribute(gemm2_tc, cudaFuncAttributeMaxDynamicSharedMemorySize, SMEM);

    // order chosen so gemm1 is our 4th launch (lands in the fixed ncu slot)
    prep_wi_gate<<<32768 + T_TOK / 8, 256>>>(tokens, gw, wi);          // 1
    rank_kernel<<<1, 1024>>>();                                        // 2
    dispatch_aP<<<dim3(KI1, MT_N, N_EXP), 256>>>(tokens);              // 3
    gemm1_tc<<<dim3(MT_N, NT1, N_EXP), 256, SMEM>>>(nullptr);          // 4
    prep_w<<<dim3(NT2, KI2, N_EXP), 256>>>(wo, /*which=*/1, I_DIM, H_DIM); // 5
    zero_kernel<<<1024, 256>>>(outp, (size_t)T_TOK * H_DIM);           // 6
    gemm2_tc<<<dim3(MT_N, NT2, N_EXP), 256, SMEM>>>(outp);             // 7
}